// round 2
// baseline (speedup 1.0000x reference)
#include <cuda_runtime.h>
#include <cuda_bf16.h>

#define IMG_H 2048
#define IMG_W 4096

// 128 MB scratch: RGBA-packed image so every cubic tap is a single LDG.128.
__device__ float4 g_packed[IMG_H * IMG_W];

// ---------------------------------------------------------------------------
// Pass 1: pack (H,W,3) f32 -> (H,W) float4 (w component unused).
// Each thread handles 4 pixels = 3 float4 loads -> 4 float4 stores (all vector).
// ---------------------------------------------------------------------------
__global__ void pack_kernel(const float* __restrict__ in) {
    int idx = blockIdx.x * blockDim.x + threadIdx.x;   // one per 4 pixels
    const float4* src = reinterpret_cast<const float4*>(in) + (size_t)idx * 3;
    float4 a = __ldg(src + 0);
    float4 b = __ldg(src + 1);
    float4 c = __ldg(src + 2);
    float4* dst = g_packed + (size_t)idx * 4;
    dst[0] = make_float4(a.x, a.y, a.z, 0.0f);
    dst[1] = make_float4(a.w, b.x, b.y, 0.0f);
    dst[2] = make_float4(b.z, b.w, c.x, 0.0f);
    dst[3] = make_float4(c.y, c.z, c.w, 0.0f);
}

// ---------------------------------------------------------------------------
// Keys cubic kernel weights (a = -0.5) for taps at {f+1, f, 1-f, 2-f}, f in [0,1).
// Closed forms: w(-1)=a f (f-1)^2 ; w(0)=(a+2)f^3-(a+3)f^2+1 ; symmetric for g=1-f.
// ---------------------------------------------------------------------------
__device__ __forceinline__ void cubic_weights(float f, float w[4]) {
    const float A = -0.5f;
    float f2 = f * f, f3 = f2 * f;
    float g = 1.0f - f;
    float g2 = g * g, g3 = g2 * g;
    w[0] = A * (f3 - 2.0f * f2 + f);
    w[1] = (A + 2.0f) * f3 - (A + 3.0f) * f2 + 1.0f;
    w[2] = (A + 2.0f) * g3 - (A + 3.0f) * g2 + 1.0f;
    w[3] = A * (g3 - 2.0f * g2 + g);
}

// Spline-upsample row of B matrix for n_ctrl=3 control points (taps clamped to [0,2]).
__device__ __forceinline__ void spline_b3(int pos, int n_out, float b[3]) {
    float u = (float)(pos * 2) / (float)(n_out - 1);
    float fi = floorf(u);
    int i0 = (int)fi;
    float w[4];
    cubic_weights(u - fi, w);
    b[0] = 0.0f; b[1] = 0.0f; b[2] = 0.0f;
#pragma unroll
    for (int k = 0; k < 4; k++) {
        int t = i0 - 1 + k;
        t = min(max(t, 0), 2);
        b[t] += w[k];
    }
}

// ---------------------------------------------------------------------------
// Pass 2: elastic warp. One thread per output pixel (3 channels).
// 16 taps, each one LDG.128 from the packed image.
// ---------------------------------------------------------------------------
__global__ void __launch_bounds__(128) warp_kernel(const float* __restrict__ disp,
                                                   float* __restrict__ out) {
    __shared__ float sD[18];   // displacement * 5 (reference scales by 5 internally)
    int tid = threadIdx.x;
    if (tid < 18) sD[tid] = 5.0f * __ldg(disp + tid);
    __syncthreads();

    int x = blockIdx.x * blockDim.x + tid;
    int y = blockIdx.y;

    // Control-point upsample weights for this row/column
    float by[3], bx[3];
    spline_b3(y, IMG_H, by);
    spline_b3(x, IMG_W, bx);

    // disp_d(y,x) = By . D_d . Bx
    float dy = 0.0f, dx = 0.0f;
#pragma unroll
    for (int j = 0; j < 3; j++) {
        float ry = 0.0f, rx = 0.0f;
#pragma unroll
        for (int k = 0; k < 3; k++) {
            ry += sD[j * 3 + k] * bx[k];
            rx += sD[9 + j * 3 + k] * bx[k];
        }
        dy += by[j] * ry;
        dx += by[j] * rx;
    }

    float yy = (float)y + dy;
    float xx = (float)x + dx;
    float fiy = floorf(yy);
    float fix = floorf(xx);
    int iy0 = (int)fiy;
    int ix0 = (int)fix;

    float wy[4], wx[4];
    cubic_weights(yy - fiy, wy);
    cubic_weights(xx - fix, wx);

    int tyc[4], txc[4];
#pragma unroll
    for (int k = 0; k < 4; k++) {
        tyc[k] = min(max(iy0 - 1 + k, 0), IMG_H - 1);
        txc[k] = min(max(ix0 - 1 + k, 0), IMG_W - 1);
    }

    float ax = 0.0f, ay = 0.0f, az = 0.0f;
#pragma unroll
    for (int a = 0; a < 4; a++) {
        const float4* row = g_packed + (size_t)tyc[a] * IMG_W;
#pragma unroll
        for (int b = 0; b < 4; b++) {
            float w = wy[a] * wx[b];
            float4 p = __ldg(row + txc[b]);
            ax += w * p.x;
            ay += w * p.y;
            az += w * p.z;
        }
    }

    size_t o = ((size_t)y * IMG_W + x) * 3;
    out[o + 0] = ax;
    out[o + 1] = ay;
    out[o + 2] = az;
}

extern "C" void kernel_launch(void* const* d_in, const int* in_sizes, int n_in,
                              void* d_out, int out_size) {
    const float* img  = (const float*)d_in[0];   // (2048, 4096, 3) f32
    const float* disp = (const float*)d_in[1];   // (2, 3, 3) f32
    float* out = (float*)d_out;                  // (2048, 4096, 3) f32

    // Pass 1: pack RGB -> RGBA (4 pixels per thread)
    int groups = IMG_H * IMG_W / 4;
    pack_kernel<<<groups / 128, 128>>>(img);

    // Pass 2: warp
    dim3 block(128, 1, 1);
    dim3 grid(IMG_W / 128, IMG_H, 1);
    warp_kernel<<<grid, block>>>(disp, out);
}

// round 4
// speedup vs baseline: 1.2681x; 1.2681x over previous
#include <cuda_runtime.h>
#include <cuda_fp16.h>

#define IMG_H 2048
#define IMG_W 4096

// 64 MB scratch: RGB0-packed fp16 image; one cubic tap = one LDG.64.
// Layout per pixel: uint2 { half2(r,g), half2(b,0) }.
__device__ uint2 g_packed[IMG_H * IMG_W];

__device__ __forceinline__ unsigned int h2u(__half2 h) {
    return *reinterpret_cast<unsigned int*>(&h);
}

// ---------------------------------------------------------------------------
// Pass 1: pack (H,W,3) f32 -> (H,W) half4 (w unused).
// Each thread handles 4 pixels: 3 float4 loads -> 2 uint4 stores.
// ---------------------------------------------------------------------------
__global__ void pack_kernel(const float* __restrict__ in) {
    int idx = blockIdx.x * blockDim.x + threadIdx.x;   // one per 4 pixels
    const float4* src = reinterpret_cast<const float4*>(in) + (size_t)idx * 3;
    float4 a = __ldg(src + 0);   // r0 g0 b0 r1
    float4 b = __ldg(src + 1);   // g1 b1 r2 g2
    float4 c = __ldg(src + 2);   // b2 r3 g3 b3

    uint4 s0, s1;
    s0.x = h2u(__floats2half2_rn(a.x, a.y));   // px0 rg
    s0.y = h2u(__floats2half2_rn(a.z, 0.0f));  // px0 b0
    s0.z = h2u(__floats2half2_rn(a.w, b.x));   // px1 rg
    s0.w = h2u(__floats2half2_rn(b.y, 0.0f));  // px1 b0
    s1.x = h2u(__floats2half2_rn(b.z, b.w));   // px2 rg
    s1.y = h2u(__floats2half2_rn(c.x, 0.0f));  // px2 b0
    s1.z = h2u(__floats2half2_rn(c.y, c.z));   // px3 rg
    s1.w = h2u(__floats2half2_rn(c.w, 0.0f));  // px3 b0

    uint4* dst = reinterpret_cast<uint4*>(g_packed + (size_t)idx * 4);
    dst[0] = s0;
    dst[1] = s1;
}

// ---------------------------------------------------------------------------
// Keys cubic kernel weights (a = -0.5) for taps at {f+1, f, 1-f, 2-f}, f in [0,1).
// ---------------------------------------------------------------------------
__device__ __forceinline__ void cubic_weights(float f, float w[4]) {
    const float A = -0.5f;
    float f2 = f * f, f3 = f2 * f;
    float g = 1.0f - f;
    float g2 = g * g, g3 = g2 * g;
    w[0] = A * (f3 - 2.0f * f2 + f);
    w[1] = (A + 2.0f) * f3 - (A + 3.0f) * f2 + 1.0f;
    w[2] = (A + 2.0f) * g3 - (A + 3.0f) * g2 + 1.0f;
    w[3] = A * (g3 - 2.0f * g2 + g);
}

// Spline-upsample row of B matrix for n_ctrl=3 control points (taps clamped to [0,2]).
__device__ __forceinline__ void spline_b3(int pos, int n_out, float b[3]) {
    float u = (float)(pos * 2) / (float)(n_out - 1);
    float fi = floorf(u);
    int i0 = (int)fi;
    float w[4];
    cubic_weights(u - fi, w);
    b[0] = 0.0f; b[1] = 0.0f; b[2] = 0.0f;
#pragma unroll
    for (int k = 0; k < 4; k++) {
        int t = i0 - 1 + k;
        t = min(max(t, 0), 2);
        b[t] += w[k];
    }
}

// ---------------------------------------------------------------------------
// Pass 2: elastic warp. One thread per output pixel (3 channels).
// 16 taps, each one LDG.64 from the fp16-packed image.
// ---------------------------------------------------------------------------
__global__ void __launch_bounds__(128) warp_kernel(const float* __restrict__ disp,
                                                   float* __restrict__ out) {
    __shared__ float sD[18];   // displacement * 5 (reference scales by 5 internally)
    int tid = threadIdx.x;
    if (tid < 18) sD[tid] = 5.0f * __ldg(disp + tid);
    __syncthreads();

    int x = blockIdx.x * blockDim.x + tid;
    int y = blockIdx.y;

    float by[3], bx[3];
    spline_b3(y, IMG_H, by);
    spline_b3(x, IMG_W, bx);

    // disp_d(y,x) = By . D_d . Bx
    float dy = 0.0f, dx = 0.0f;
#pragma unroll
    for (int j = 0; j < 3; j++) {
        float ry = 0.0f, rx = 0.0f;
#pragma unroll
        for (int k = 0; k < 3; k++) {
            ry += sD[j * 3 + k] * bx[k];
            rx += sD[9 + j * 3 + k] * bx[k];
        }
        dy += by[j] * ry;
        dx += by[j] * rx;
    }

    float yy = (float)y + dy;
    float xx = (float)x + dx;
    float fiy = floorf(yy);
    float fix = floorf(xx);
    int iy0 = (int)fiy;
    int ix0 = (int)fix;

    float wy[4], wx[4];
    cubic_weights(yy - fiy, wy);
    cubic_weights(xx - fix, wx);

    int tyc[4], txc[4];
#pragma unroll
    for (int k = 0; k < 4; k++) {
        tyc[k] = min(max(iy0 - 1 + k, 0), IMG_H - 1);
        txc[k] = min(max(ix0 - 1 + k, 0), IMG_W - 1);
    }

    float ax = 0.0f, ay = 0.0f, az = 0.0f;
#pragma unroll
    for (int a = 0; a < 4; a++) {
        const uint2* row = g_packed + (size_t)tyc[a] * IMG_W;
#pragma unroll
        for (int b = 0; b < 4; b++) {
            float w = wy[a] * wx[b];
            uint2 q = __ldg(row + txc[b]);
            __half2 rg = *reinterpret_cast<__half2*>(&q.x);
            __half2 b0 = *reinterpret_cast<__half2*>(&q.y);
            float2 frg = __half22float2(rg);
            float  fb  = __low2float(b0);
            ax += w * frg.x;
            ay += w * frg.y;
            az += w * fb;
        }
    }

    size_t o = ((size_t)y * IMG_W + x) * 3;
    out[o + 0] = ax;
    out[o + 1] = ay;
    out[o + 2] = az;
}

extern "C" void kernel_launch(void* const* d_in, const int* in_sizes, int n_in,
                              void* d_out, int out_size) {
    const float* img  = (const float*)d_in[0];   // (2048, 4096, 3) f32
    const float* disp = (const float*)d_in[1];   // (2, 3, 3) f32
    float* out = (float*)d_out;                  // (2048, 4096, 3) f32

    // Pass 1: pack RGB -> fp16 RGB0 (4 pixels per thread)
    int groups = IMG_H * IMG_W / 4;
    pack_kernel<<<groups / 128, 128>>>(img);

    // Pass 2: warp
    dim3 block(128, 1, 1);
    dim3 grid(IMG_W / 128, IMG_H, 1);
    warp_kernel<<<grid, block>>>(disp, out);
}

// round 5
// speedup vs baseline: 1.5918x; 1.2553x over previous
#include <cuda_runtime.h>
#include <cuda_fp16.h>

#define IMG_H 2048
#define IMG_W 4096

// 64 MB scratch: RGB0-packed fp16 image; one cubic tap = one LDG.64.
// Layout per pixel: uint2 { half2(r,g), half2(b,0) }.
__device__ uint2 g_packed[IMG_H * IMG_W];

__device__ __forceinline__ unsigned int h2u(__half2 h) {
    return *reinterpret_cast<unsigned int*>(&h);
}

// ---------------------------------------------------------------------------
// Pass 1: pack (H,W,3) f32 -> (H,W) half4 (w unused).
// ---------------------------------------------------------------------------
__global__ void pack_kernel(const float* __restrict__ in) {
    int idx = blockIdx.x * blockDim.x + threadIdx.x;   // one per 4 pixels
    const float4* src = reinterpret_cast<const float4*>(in) + (size_t)idx * 3;
    float4 a = __ldg(src + 0);   // r0 g0 b0 r1
    float4 b = __ldg(src + 1);   // g1 b1 r2 g2
    float4 c = __ldg(src + 2);   // b2 r3 g3 b3

    uint4 s0, s1;
    s0.x = h2u(__floats2half2_rn(a.x, a.y));
    s0.y = h2u(__floats2half2_rn(a.z, 0.0f));
    s0.z = h2u(__floats2half2_rn(a.w, b.x));
    s0.w = h2u(__floats2half2_rn(b.y, 0.0f));
    s1.x = h2u(__floats2half2_rn(b.z, b.w));
    s1.y = h2u(__floats2half2_rn(c.x, 0.0f));
    s1.z = h2u(__floats2half2_rn(c.y, c.z));
    s1.w = h2u(__floats2half2_rn(c.w, 0.0f));

    uint4* dst = reinterpret_cast<uint4*>(g_packed + (size_t)idx * 4);
    dst[0] = s0;
    dst[1] = s1;
}

// ---------------------------------------------------------------------------
// Keys cubic weights (A=-0.5) for taps {i0-1, i0, i0+1, i0+2}, f = frac in [0,1).
// Closed forms + partition-of-unity for w2.
// ---------------------------------------------------------------------------
__device__ __forceinline__ void cubic_weights(float f, float w[4]) {
    float g = 1.0f - f;
    w[0] = -0.5f * (f * (g * g));
    w[1] = fmaf(fmaf(1.5f, f, -2.5f) * f, f, 1.0f);   // 1.5 f^3 - 2.5 f^2 + 1
    w[3] = -0.5f * (g * (f * f));
    w[2] = 1.0f - w[0] - w[1] - w[3];
}

// Spline-upsample row of B matrix for n_ctrl=3 control points (taps clamped to [0,2]).
__device__ __forceinline__ void spline_b3(int pos, int n_out, float b[3]) {
    float u = (float)(pos * 2) / (float)(n_out - 1);
    float fi = floorf(u);
    int i0 = (int)fi;
    float w[4];
    cubic_weights(u - fi, w);
    b[0] = 0.0f; b[1] = 0.0f; b[2] = 0.0f;
#pragma unroll
    for (int k = 0; k < 4; k++) {
        int t = i0 - 1 + k;
        t = min(max(t, 0), 2);
        b[t] += w[k];
    }
}

// One tap: accumulate w * pixel into (ax, ay, az).
__device__ __forceinline__ void tap(const uint2* p, float w,
                                    float& ax, float& ay, float& az) {
    uint2 q = __ldg(p);
    __half2 rg = *reinterpret_cast<__half2*>(&q.x);
    __half2 b0 = *reinterpret_cast<__half2*>(&q.y);
    float2 frg = __half22float2(rg);
    float  fb  = __low2float(b0);
    ax = fmaf(w, frg.x, ax);
    ay = fmaf(w, frg.y, ay);
    az = fmaf(w, fb,  az);
}

// ---------------------------------------------------------------------------
// Pass 2: elastic warp. One thread per output pixel.
// y-spline and displacement row-contraction hoisted to per-block smem.
// ---------------------------------------------------------------------------
__global__ void __launch_bounds__(128) warp_kernel(const float* __restrict__ disp,
                                                   float* __restrict__ out) {
    __shared__ float sWy[4];   // y cubic weights for this row
    __shared__ int   sTy[4];   // clamped y tap rows
    __shared__ float sC[6];    // c[d][k] = 5 * sum_j by[j] * D[d,j,k]

    int tid = threadIdx.x;
    int y = blockIdx.y;

    if (tid == 0) {
        float by[3];
        spline_b3(y, IMG_H, by);
#pragma unroll
        for (int d = 0; d < 2; d++)
#pragma unroll
            for (int k = 0; k < 3; k++) {
                float c = 0.0f;
#pragma unroll
                for (int j = 0; j < 3; j++)
                    c = fmaf(by[j], __ldg(disp + d * 9 + j * 3 + k), c);
                sC[d * 3 + k] = 5.0f * c;
            }
    }
    __syncthreads();

    int x = blockIdx.x * blockDim.x + tid;

    float bx[3];
    spline_b3(x, IMG_W, bx);

    float dy = fmaf(sC[0], bx[0], fmaf(sC[1], bx[1], sC[2] * bx[2]));
    float dx = fmaf(sC[3], bx[0], fmaf(sC[4], bx[1], sC[5] * bx[2]));

    float yy = (float)y + dy;
    float xx = (float)x + dx;
    float fiy = floorf(yy);
    float fix = floorf(xx);
    int iy0 = (int)fiy;
    int ix0 = (int)fix;

    float wy[4], wx[4];
    cubic_weights(yy - fiy, wy);
    cubic_weights(xx - fix, wx);

    float ax = 0.0f, ay = 0.0f, az = 0.0f;

    bool interior = (iy0 >= 1) && (iy0 <= IMG_H - 3) && (ix0 >= 1) && (ix0 <= IMG_W - 3);
    if (interior) {
        const uint2* base = g_packed + (size_t)(iy0 - 1) * IMG_W + (ix0 - 1);
#pragma unroll
        for (int a = 0; a < 4; a++) {
            float rx = 0.0f, ry = 0.0f, rz = 0.0f;
#pragma unroll
            for (int b = 0; b < 4; b++)
                tap(base + b, wx[b], rx, ry, rz);
            ax = fmaf(wy[a], rx, ax);
            ay = fmaf(wy[a], ry, ay);
            az = fmaf(wy[a], rz, az);
            base += IMG_W;
        }
    } else {
        int tyc[4], txc[4];
#pragma unroll
        for (int k = 0; k < 4; k++) {
            tyc[k] = min(max(iy0 - 1 + k, 0), IMG_H - 1);
            txc[k] = min(max(ix0 - 1 + k, 0), IMG_W - 1);
        }
#pragma unroll
        for (int a = 0; a < 4; a++) {
            const uint2* row = g_packed + (size_t)tyc[a] * IMG_W;
            float rx = 0.0f, ry = 0.0f, rz = 0.0f;
#pragma unroll
            for (int b = 0; b < 4; b++)
                tap(row + txc[b], wx[b], rx, ry, rz);
            ax = fmaf(wy[a], rx, ax);
            ay = fmaf(wy[a], ry, ay);
            az = fmaf(wy[a], rz, az);
        }
    }

    size_t o = ((size_t)y * IMG_W + x) * 3;
    out[o + 0] = ax;
    out[o + 1] = ay;
    out[o + 2] = az;
}

extern "C" void kernel_launch(void* const* d_in, const int* in_sizes, int n_in,
                              void* d_out, int out_size) {
    const float* img  = (const float*)d_in[0];   // (2048, 4096, 3) f32
    const float* disp = (const float*)d_in[1];   // (2, 3, 3) f32
    float* out = (float*)d_out;                  // (2048, 4096, 3) f32

    int groups = IMG_H * IMG_W / 4;
    pack_kernel<<<groups / 128, 128>>>(img);

    dim3 block(128, 1, 1);
    dim3 grid(IMG_W / 128, IMG_H, 1);
    warp_kernel<<<grid, block>>>(disp, out);
}

// round 7
// speedup vs baseline: 1.7117x; 1.0753x over previous
#include <cuda_runtime.h>
#include <cuda_fp16.h>

#define IMG_H 2048
#define IMG_W 4096

// 64 MB scratch: RGB0-packed fp16 image; one cubic tap = one LDG.64.
__device__ uint2 g_packed[IMG_H * IMG_W];

__device__ __forceinline__ unsigned int h2u(__half2 h) {
    return *reinterpret_cast<unsigned int*>(&h);
}

// ---------------------------------------------------------------------------
// Pass 1: pack (H,W,3) f32 -> (H,W) half4 (w unused).
// ---------------------------------------------------------------------------
__global__ void pack_kernel(const float* __restrict__ in) {
    int idx = blockIdx.x * blockDim.x + threadIdx.x;   // one per 4 pixels
    const float4* src = reinterpret_cast<const float4*>(in) + (size_t)idx * 3;
    float4 a = __ldg(src + 0);
    float4 b = __ldg(src + 1);
    float4 c = __ldg(src + 2);

    uint4 s0, s1;
    s0.x = h2u(__floats2half2_rn(a.x, a.y));
    s0.y = h2u(__floats2half2_rn(a.z, 0.0f));
    s0.z = h2u(__floats2half2_rn(a.w, b.x));
    s0.w = h2u(__floats2half2_rn(b.y, 0.0f));
    s1.x = h2u(__floats2half2_rn(b.z, b.w));
    s1.y = h2u(__floats2half2_rn(c.x, 0.0f));
    s1.z = h2u(__floats2half2_rn(c.y, c.z));
    s1.w = h2u(__floats2half2_rn(c.w, 0.0f));

    uint4* dst = reinterpret_cast<uint4*>(g_packed + (size_t)idx * 4);
    dst[0] = s0;
    dst[1] = s1;
}

// ---------------------------------------------------------------------------
// Keys cubic weights (A=-0.5), taps {i0-1..i0+2}, f in [0,1).
// ---------------------------------------------------------------------------
__device__ __forceinline__ void cubic_weights(float f, float w[4]) {
    float g = 1.0f - f;
    w[0] = -0.5f * (f * (g * g));
    w[1] = fmaf(fmaf(1.5f, f, -2.5f) * f, f, 1.0f);
    w[3] = -0.5f * (g * (f * f));
    w[2] = 1.0f - w[0] - w[1] - w[3];
}

__device__ __forceinline__ void spline_b3(int pos, int n_out, float b[3]) {
    float u = (float)(pos * 2) / (float)(n_out - 1);
    float fi = floorf(u);
    int i0 = (int)fi;
    float w[4];
    cubic_weights(u - fi, w);
    b[0] = 0.0f; b[1] = 0.0f; b[2] = 0.0f;
#pragma unroll
    for (int k = 0; k < 4; k++) {
        int t = i0 - 1 + k;
        t = min(max(t, 0), 2);
        b[t] += w[k];
    }
}

// Load + convert one row of 4 taps (interior, contiguous).
__device__ __forceinline__ void load_row(const uint2* __restrict__ p, float3 v[4]) {
#pragma unroll
    for (int b = 0; b < 4; b++) {
        uint2 q = __ldg(p + b);
        __half2 rg = *reinterpret_cast<__half2*>(&q.x);
        __half2 bb = *reinterpret_cast<__half2*>(&q.y);
        float2 frg = __half22float2(rg);
        v[b].x = frg.x;
        v[b].y = frg.y;
        v[b].z = __low2float(bb);
    }
}

__device__ __forceinline__ float3 rowsum(const float3 v[4], const float wx[4]) {
    float3 s = make_float3(0.f, 0.f, 0.f);
#pragma unroll
    for (int b = 0; b < 4; b++) {
        s.x = fmaf(wx[b], v[b].x, s.x);
        s.y = fmaf(wx[b], v[b].y, s.y);
        s.z = fmaf(wx[b], v[b].z, s.z);
    }
    return s;
}

// Rare-path sampler: fully clamped 16-tap cubic. Kept out of the hot I$ stream.
__device__ __noinline__ float3 sample_clamped(float yy, float xx) {
    float fiy = floorf(yy), fix = floorf(xx);
    int iy0 = (int)fiy, ix0 = (int)fix;
    float wy[4], wx[4];
    cubic_weights(yy - fiy, wy);
    cubic_weights(xx - fix, wx);
    int tyc[4], txc[4];
#pragma unroll
    for (int k = 0; k < 4; k++) {
        tyc[k] = min(max(iy0 - 1 + k, 0), IMG_H - 1);
        txc[k] = min(max(ix0 - 1 + k, 0), IMG_W - 1);
    }
    float3 acc = make_float3(0.f, 0.f, 0.f);
#pragma unroll
    for (int a = 0; a < 4; a++) {
        const uint2* row = g_packed + (size_t)tyc[a] * IMG_W;
        float3 s = make_float3(0.f, 0.f, 0.f);
#pragma unroll
        for (int b = 0; b < 4; b++) {
            uint2 q = __ldg(row + txc[b]);
            __half2 rg = *reinterpret_cast<__half2*>(&q.x);
            __half2 bb = *reinterpret_cast<__half2*>(&q.y);
            float2 frg = __half22float2(rg);
            s.x = fmaf(wx[b], frg.x, s.x);
            s.y = fmaf(wx[b], frg.y, s.y);
            s.z = fmaf(wx[b], __low2float(bb), s.z);
        }
        acc.x = fmaf(wy[a], s.x, acc.x);
        acc.y = fmaf(wy[a], s.y, acc.y);
        acc.z = fmaf(wy[a], s.z, acc.z);
    }
    return acc;
}

// ---------------------------------------------------------------------------
// Pass 2: elastic warp. One thread per VERTICAL pixel pair (y0=2*by, y0+1).
// When the pair's tap windows align (iy advances by 1, ix unchanged — ~97% of
// threads), load 5 shared rows instead of 8: middle 3 rows loaded/converted
// once, reduced twice with each pixel's own exact wx weights.
// ---------------------------------------------------------------------------
__global__ void __launch_bounds__(128) warp_kernel(const float* __restrict__ disp,
                                                   float* __restrict__ out) {
    __shared__ float sC[12];   // rows y0,y1: c[d][k] = 5 * sum_j by[j]*D[d,j,k]

    int tid = threadIdx.x;
    int y0 = blockIdx.y * 2;

    if (tid < 2) {
        float by[3];
        spline_b3(y0 + tid, IMG_H, by);
#pragma unroll
        for (int d = 0; d < 2; d++)
#pragma unroll
            for (int k = 0; k < 3; k++) {
                float c = 0.0f;
#pragma unroll
                for (int j = 0; j < 3; j++)
                    c = fmaf(by[j], __ldg(disp + d * 9 + j * 3 + k), c);
                sC[tid * 6 + d * 3 + k] = 5.0f * c;
            }
    }
    __syncthreads();

    int x = blockIdx.x * blockDim.x + tid;

    float bx[3];
    spline_b3(x, IMG_W, bx);

    float dy0 = fmaf(sC[0], bx[0], fmaf(sC[1], bx[1], sC[2] * bx[2]));
    float dx0 = fmaf(sC[3], bx[0], fmaf(sC[4], bx[1], sC[5] * bx[2]));
    float dy1 = fmaf(sC[6], bx[0], fmaf(sC[7], bx[1], sC[8] * bx[2]));
    float dx1 = fmaf(sC[9], bx[0], fmaf(sC[10], bx[1], sC[11] * bx[2]));

    float yy0 = (float)y0 + dy0;
    float xx0 = (float)x + dx0;
    float yy1 = (float)(y0 + 1) + dy1;
    float xx1 = (float)x + dx1;

    float fiy0 = floorf(yy0), fix0 = floorf(xx0);
    float fiy1 = floorf(yy1), fix1 = floorf(xx1);
    int iy0 = (int)fiy0, ix0 = (int)fix0;
    int iy1 = (int)fiy1, ix1 = (int)fix1;

    float3 acc0, acc1;

    bool share = (iy1 == iy0 + 1) && (ix1 == ix0) &&
                 (iy0 >= 1) && (iy0 <= IMG_H - 5) &&
                 (ix0 >= 1) && (ix0 <= IMG_W - 3);

    if (share) {
        float wy0[4], wy1[4], wx0[4], wx1[4];
        cubic_weights(yy0 - fiy0, wy0);
        cubic_weights(yy1 - fiy1, wy1);
        cubic_weights(xx0 - fix0, wx0);
        cubic_weights(xx1 - fix1, wx1);

        const uint2* base = g_packed + (size_t)(iy0 - 1) * IMG_W + (ix0 - 1);
        float3 v[4];
        acc0 = make_float3(0.f, 0.f, 0.f);
        acc1 = make_float3(0.f, 0.f, 0.f);

        // row 0: only pixel 0
        load_row(base, v);
        {
            float3 s = rowsum(v, wx0);
            acc0.x = fmaf(wy0[0], s.x, acc0.x);
            acc0.y = fmaf(wy0[0], s.y, acc0.y);
            acc0.z = fmaf(wy0[0], s.z, acc0.z);
        }
        base += IMG_W;
        // rows 1..3: shared by both pixels
#pragma unroll
        for (int r = 1; r < 4; r++) {
            load_row(base, v);
            float3 s0 = rowsum(v, wx0);
            float3 s1 = rowsum(v, wx1);
            acc0.x = fmaf(wy0[r], s0.x, acc0.x);
            acc0.y = fmaf(wy0[r], s0.y, acc0.y);
            acc0.z = fmaf(wy0[r], s0.z, acc0.z);
            acc1.x = fmaf(wy1[r - 1], s1.x, acc1.x);
            acc1.y = fmaf(wy1[r - 1], s1.y, acc1.y);
            acc1.z = fmaf(wy1[r - 1], s1.z, acc1.z);
            base += IMG_W;
        }
        // row 4: only pixel 1
        load_row(base, v);
        {
            float3 s = rowsum(v, wx1);
            acc1.x = fmaf(wy1[3], s.x, acc1.x);
            acc1.y = fmaf(wy1[3], s.y, acc1.y);
            acc1.z = fmaf(wy1[3], s.z, acc1.z);
        }
    } else {
        acc0 = sample_clamped(yy0, xx0);
        acc1 = sample_clamped(yy1, xx1);
    }

    size_t o0 = ((size_t)y0 * IMG_W + x) * 3;
    out[o0 + 0] = acc0.x;
    out[o0 + 1] = acc0.y;
    out[o0 + 2] = acc0.z;
    size_t o1 = o0 + (size_t)IMG_W * 3;
    out[o1 + 0] = acc1.x;
    out[o1 + 1] = acc1.y;
    out[o1 + 2] = acc1.z;
}

extern "C" void kernel_launch(void* const* d_in, const int* in_sizes, int n_in,
                              void* d_out, int out_size) {
    const float* img  = (const float*)d_in[0];   // (2048, 4096, 3) f32
    const float* disp = (const float*)d_in[1];   // (2, 3, 3) f32
    float* out = (float*)d_out;                  // (2048, 4096, 3) f32

    int groups = IMG_H * IMG_W / 4;
    pack_kernel<<<groups / 128, 128>>>(img);

    dim3 block(128, 1, 1);
    dim3 grid(IMG_W / 128, IMG_H / 2, 1);
    warp_kernel<<<grid, block>>>(disp, out);
}

// round 8
// speedup vs baseline: 1.8192x; 1.0628x over previous
#include <cuda_runtime.h>
#include <cuda_fp16.h>

#define IMG_H 2048
#define IMG_W 4096

// 64 MB scratch: RGB0-packed fp16 image; one cubic tap = one LDG.64.
__device__ uint2 g_packed[IMG_H * IMG_W];

__device__ __forceinline__ unsigned int h2u(__half2 h) {
    return *reinterpret_cast<unsigned int*>(&h);
}

// ---------------------------------------------------------------------------
// Pass 1: pack (H,W,3) f32 -> (H,W) half4 (w unused).
// ---------------------------------------------------------------------------
__global__ void pack_kernel(const float* __restrict__ in) {
    int idx = blockIdx.x * blockDim.x + threadIdx.x;   // one per 4 pixels
    const float4* src = reinterpret_cast<const float4*>(in) + (size_t)idx * 3;
    float4 a = __ldg(src + 0);
    float4 b = __ldg(src + 1);
    float4 c = __ldg(src + 2);

    uint4 s0, s1;
    s0.x = h2u(__floats2half2_rn(a.x, a.y));
    s0.y = h2u(__floats2half2_rn(a.z, 0.0f));
    s0.z = h2u(__floats2half2_rn(a.w, b.x));
    s0.w = h2u(__floats2half2_rn(b.y, 0.0f));
    s1.x = h2u(__floats2half2_rn(b.z, b.w));
    s1.y = h2u(__floats2half2_rn(c.x, 0.0f));
    s1.z = h2u(__floats2half2_rn(c.y, c.z));
    s1.w = h2u(__floats2half2_rn(c.w, 0.0f));

    uint4* dst = reinterpret_cast<uint4*>(g_packed + (size_t)idx * 4);
    dst[0] = s0;
    dst[1] = s1;
}

// ---------------------------------------------------------------------------
// Keys cubic weights (A=-0.5), taps {i0-1..i0+2}, f in [0,1).
// ---------------------------------------------------------------------------
__device__ __forceinline__ void cubic_weights(float f, float w[4]) {
    float g = 1.0f - f;
    w[0] = -0.5f * (f * (g * g));
    w[1] = fmaf(fmaf(1.5f, f, -2.5f) * f, f, 1.0f);
    w[3] = -0.5f * (g * (f * f));
    w[2] = 1.0f - w[0] - w[1] - w[3];
}

__device__ __forceinline__ void spline_b3(int pos, int n_out, float b[3]) {
    float u = (float)(pos * 2) / (float)(n_out - 1);
    float fi = floorf(u);
    int i0 = (int)fi;
    float w[4];
    cubic_weights(u - fi, w);
    b[0] = 0.0f; b[1] = 0.0f; b[2] = 0.0f;
#pragma unroll
    for (int k = 0; k < 4; k++) {
        int t = i0 - 1 + k;
        t = min(max(t, 0), 2);
        b[t] += w[k];
    }
}

// Load + convert one row of 4 taps (interior, contiguous).
__device__ __forceinline__ void load_row(const uint2* __restrict__ p, float3 v[4]) {
#pragma unroll
    for (int b = 0; b < 4; b++) {
        uint2 q = __ldg(p + b);
        __half2 rg = *reinterpret_cast<__half2*>(&q.x);
        __half2 bb = *reinterpret_cast<__half2*>(&q.y);
        float2 frg = __half22float2(rg);
        v[b].x = frg.x;
        v[b].y = frg.y;
        v[b].z = __low2float(bb);
    }
}

__device__ __forceinline__ float3 rowsum(const float3 v[4], const float wx[4]) {
    float3 s = make_float3(0.f, 0.f, 0.f);
#pragma unroll
    for (int b = 0; b < 4; b++) {
        s.x = fmaf(wx[b], v[b].x, s.x);
        s.y = fmaf(wx[b], v[b].y, s.y);
        s.z = fmaf(wx[b], v[b].z, s.z);
    }
    return s;
}

// Rare-path sampler: fully clamped 16-tap cubic. Kept out of the hot I$ stream.
__device__ __noinline__ float3 sample_clamped(float yy, float xx) {
    float fiy = floorf(yy), fix = floorf(xx);
    int iy0 = (int)fiy, ix0 = (int)fix;
    float wy[4], wx[4];
    cubic_weights(yy - fiy, wy);
    cubic_weights(xx - fix, wx);
    int tyc[4], txc[4];
#pragma unroll
    for (int k = 0; k < 4; k++) {
        tyc[k] = min(max(iy0 - 1 + k, 0), IMG_H - 1);
        txc[k] = min(max(ix0 - 1 + k, 0), IMG_W - 1);
    }
    float3 acc = make_float3(0.f, 0.f, 0.f);
#pragma unroll
    for (int a = 0; a < 4; a++) {
        const uint2* row = g_packed + (size_t)tyc[a] * IMG_W;
        float3 s = make_float3(0.f, 0.f, 0.f);
#pragma unroll
        for (int b = 0; b < 4; b++) {
            uint2 q = __ldg(row + txc[b]);
            __half2 rg = *reinterpret_cast<__half2*>(&q.x);
            __half2 bb = *reinterpret_cast<__half2*>(&q.y);
            float2 frg = __half22float2(rg);
            s.x = fmaf(wx[b], frg.x, s.x);
            s.y = fmaf(wx[b], frg.y, s.y);
            s.z = fmaf(wx[b], __low2float(bb), s.z);
        }
        acc.x = fmaf(wy[a], s.x, acc.x);
        acc.y = fmaf(wy[a], s.y, acc.y);
        acc.z = fmaf(wy[a], s.z, acc.z);
    }
    return acc;
}

// ---------------------------------------------------------------------------
// Pass 2: elastic warp. One thread per VERTICAL 4-pixel quad (y0=4*by .. y0+3).
// When all windows align (iy advances by 1 each row, ix constant — ~90%+ of
// threads), the 4 pixels' 16 tap rows collapse to 7 shared rows, each
// loaded/converted once and reduced with each pixel's own exact weights.
// ---------------------------------------------------------------------------
__global__ void __launch_bounds__(128) warp_kernel(const float* __restrict__ disp,
                                                   float* __restrict__ out) {
    __shared__ float sC[24];   // rows y0..y0+3: c[d][k] = 5 * sum_j by[j]*D[d,j,k]

    int tid = threadIdx.x;
    int y0 = blockIdx.y * 4;

    if (tid < 4) {
        float by[3];
        spline_b3(y0 + tid, IMG_H, by);
#pragma unroll
        for (int d = 0; d < 2; d++)
#pragma unroll
            for (int k = 0; k < 3; k++) {
                float c = 0.0f;
#pragma unroll
                for (int j = 0; j < 3; j++)
                    c = fmaf(by[j], __ldg(disp + d * 9 + j * 3 + k), c);
                sC[tid * 6 + d * 3 + k] = 5.0f * c;
            }
    }
    __syncthreads();

    int x = blockIdx.x * blockDim.x + tid;

    float bx[3];
    spline_b3(x, IMG_W, bx);

    float yy[4], xx[4];
    int iy[4], ix[4];
    float fy[4], fx[4];
#pragma unroll
    for (int p = 0; p < 4; p++) {
        float dyp = fmaf(sC[p * 6 + 0], bx[0], fmaf(sC[p * 6 + 1], bx[1], sC[p * 6 + 2] * bx[2]));
        float dxp = fmaf(sC[p * 6 + 3], bx[0], fmaf(sC[p * 6 + 4], bx[1], sC[p * 6 + 5] * bx[2]));
        yy[p] = (float)(y0 + p) + dyp;
        xx[p] = (float)x + dxp;
        float fiy = floorf(yy[p]);
        float fix = floorf(xx[p]);
        iy[p] = (int)fiy;
        ix[p] = (int)fix;
        fy[p] = yy[p] - fiy;
        fx[p] = xx[p] - fix;
    }

    float3 acc[4];

    bool share = (iy[1] == iy[0] + 1) && (iy[2] == iy[0] + 2) && (iy[3] == iy[0] + 3) &&
                 (ix[1] == ix[0]) && (ix[2] == ix[0]) && (ix[3] == ix[0]) &&
                 (iy[0] >= 1) && (iy[0] <= IMG_H - 7) &&
                 (ix[0] >= 1) && (ix[0] <= IMG_W - 3);

    if (share) {
        float wy[4][4], wx[4][4];
#pragma unroll
        for (int p = 0; p < 4; p++) {
            cubic_weights(fy[p], wy[p]);
            cubic_weights(fx[p], wx[p]);
            acc[p] = make_float3(0.f, 0.f, 0.f);
        }

        const uint2* base = g_packed + (size_t)(iy[0] - 1) * IMG_W + (ix[0] - 1);
        float3 v[4];

        // 7 shared rows; row r serves pixels p in [max(0,r-3), min(3,r)],
        // pixel p's wy index for row r is (r - p).
#pragma unroll
        for (int r = 0; r < 7; r++) {
            load_row(base, v);
#pragma unroll
            for (int p = 0; p < 4; p++) {
                if (p >= r - 3 && p <= r) {
                    float3 s = rowsum(v, wx[p]);
                    float w = wy[p][r - p];
                    acc[p].x = fmaf(w, s.x, acc[p].x);
                    acc[p].y = fmaf(w, s.y, acc[p].y);
                    acc[p].z = fmaf(w, s.z, acc[p].z);
                }
            }
            base += IMG_W;
        }
    } else {
#pragma unroll
        for (int p = 0; p < 4; p++)
            acc[p] = sample_clamped(yy[p], xx[p]);
    }

    size_t o = ((size_t)y0 * IMG_W + x) * 3;
#pragma unroll
    for (int p = 0; p < 4; p++) {
        out[o + 0] = acc[p].x;
        out[o + 1] = acc[p].y;
        out[o + 2] = acc[p].z;
        o += (size_t)IMG_W * 3;
    }
}

extern "C" void kernel_launch(void* const* d_in, const int* in_sizes, int n_in,
                              void* d_out, int out_size) {
    const float* img  = (const float*)d_in[0];   // (2048, 4096, 3) f32
    const float* disp = (const float*)d_in[1];   // (2, 3, 3) f32
    float* out = (float*)d_out;                  // (2048, 4096, 3) f32

    int groups = IMG_H * IMG_W / 4;
    pack_kernel<<<groups / 128, 128>>>(img);

    dim3 block(128, 1, 1);
    dim3 grid(IMG_W / 128, IMG_H / 4, 1);
    warp_kernel<<<grid, block>>>(disp, out);
}

// round 9
// speedup vs baseline: 1.8511x; 1.0175x over previous
#include <cuda_runtime.h>
#include <cuda_fp16.h>

#define IMG_H 2048
#define IMG_W 4096

// 64 MB scratch: RGB0-packed fp16 image; one cubic tap = one LDG.64.
__device__ uint2 g_packed[IMG_H * IMG_W];

__device__ __forceinline__ unsigned int h2u(__half2 h) {
    return *reinterpret_cast<unsigned int*>(&h);
}

// ---------------------------------------------------------------------------
// Pass 1: pack (H,W,3) f32 -> (H,W) half4 (w unused).
// ---------------------------------------------------------------------------
__global__ void pack_kernel(const float* __restrict__ in) {
    int idx = blockIdx.x * blockDim.x + threadIdx.x;   // one per 4 pixels
    const float4* src = reinterpret_cast<const float4*>(in) + (size_t)idx * 3;
    float4 a = __ldg(src + 0);
    float4 b = __ldg(src + 1);
    float4 c = __ldg(src + 2);

    uint4 s0, s1;
    s0.x = h2u(__floats2half2_rn(a.x, a.y));
    s0.y = h2u(__floats2half2_rn(a.z, 0.0f));
    s0.z = h2u(__floats2half2_rn(a.w, b.x));
    s0.w = h2u(__floats2half2_rn(b.y, 0.0f));
    s1.x = h2u(__floats2half2_rn(b.z, b.w));
    s1.y = h2u(__floats2half2_rn(c.x, 0.0f));
    s1.z = h2u(__floats2half2_rn(c.y, c.z));
    s1.w = h2u(__floats2half2_rn(c.w, 0.0f));

    uint4* dst = reinterpret_cast<uint4*>(g_packed + (size_t)idx * 4);
    dst[0] = s0;
    dst[1] = s1;
}

// ---------------------------------------------------------------------------
// Keys cubic weights (A=-0.5), taps {i0-1..i0+2}, f in [0,1).
// ---------------------------------------------------------------------------
__device__ __forceinline__ void cubic_weights(float f, float w[4]) {
    float g = 1.0f - f;
    w[0] = -0.5f * (f * (g * g));
    w[1] = fmaf(fmaf(1.5f, f, -2.5f) * f, f, 1.0f);
    w[3] = -0.5f * (g * (f * f));
    w[2] = 1.0f - w[0] - w[1] - w[3];
}

__device__ __forceinline__ void spline_b3(int pos, int n_out, float b[3]) {
    float u = (float)(pos * 2) / (float)(n_out - 1);
    float fi = floorf(u);
    int i0 = (int)fi;
    float w[4];
    cubic_weights(u - fi, w);
    b[0] = 0.0f; b[1] = 0.0f; b[2] = 0.0f;
#pragma unroll
    for (int k = 0; k < 4; k++) {
        int t = i0 - 1 + k;
        t = min(max(t, 0), 2);
        b[t] += w[k];
    }
}

__device__ __forceinline__ void convert_row(const uint2 raw[4], float3 v[4]) {
#pragma unroll
    for (int b = 0; b < 4; b++) {
        uint2 q = raw[b];
        __half2 rg = *reinterpret_cast<const __half2*>(&q.x);
        __half2 bb = *reinterpret_cast<const __half2*>(&q.y);
        float2 frg = __half22float2(rg);
        v[b].x = frg.x;
        v[b].y = frg.y;
        v[b].z = __low2float(bb);
    }
}

__device__ __forceinline__ float3 rowsum(const float3 v[4], const float wx[4]) {
    float3 s = make_float3(0.f, 0.f, 0.f);
#pragma unroll
    for (int b = 0; b < 4; b++) {
        s.x = fmaf(wx[b], v[b].x, s.x);
        s.y = fmaf(wx[b], v[b].y, s.y);
        s.z = fmaf(wx[b], v[b].z, s.z);
    }
    return s;
}

// Rare-path sampler: fully clamped 16-tap cubic. Kept out of the hot I$ stream.
__device__ __noinline__ float3 sample_clamped(float yy, float xx) {
    float fiy = floorf(yy), fix = floorf(xx);
    int iy0 = (int)fiy, ix0 = (int)fix;
    float wy[4], wx[4];
    cubic_weights(yy - fiy, wy);
    cubic_weights(xx - fix, wx);
    int tyc[4], txc[4];
#pragma unroll
    for (int k = 0; k < 4; k++) {
        tyc[k] = min(max(iy0 - 1 + k, 0), IMG_H - 1);
        txc[k] = min(max(ix0 - 1 + k, 0), IMG_W - 1);
    }
    float3 acc = make_float3(0.f, 0.f, 0.f);
#pragma unroll
    for (int a = 0; a < 4; a++) {
        const uint2* row = g_packed + (size_t)tyc[a] * IMG_W;
        float3 s = make_float3(0.f, 0.f, 0.f);
#pragma unroll
        for (int b = 0; b < 4; b++) {
            uint2 q = __ldg(row + txc[b]);
            __half2 rg = *reinterpret_cast<__half2*>(&q.x);
            __half2 bb = *reinterpret_cast<__half2*>(&q.y);
            float2 frg = __half22float2(rg);
            s.x = fmaf(wx[b], frg.x, s.x);
            s.y = fmaf(wx[b], frg.y, s.y);
            s.z = fmaf(wx[b], __low2float(bb), s.z);
        }
        acc.x = fmaf(wy[a], s.x, acc.x);
        acc.y = fmaf(wy[a], s.y, acc.y);
        acc.z = fmaf(wy[a], s.z, acc.z);
    }
    return acc;
}

// ---------------------------------------------------------------------------
// Pass 2: elastic warp. One thread per VERTICAL 4-pixel quad (y0=4*by .. y0+3).
// Shared-window fast path: 7 rows serve all 4 pixels. Loads are software-
// pipelined one row ahead (double raw buffer) to hide L1 latency.
// ---------------------------------------------------------------------------
__global__ void __launch_bounds__(128, 8) warp_kernel(const float* __restrict__ disp,
                                                      float* __restrict__ out) {
    __shared__ float sC[24];   // rows y0..y0+3: c[d][k] = 5 * sum_j by[j]*D[d,j,k]

    int tid = threadIdx.x;
    int y0 = blockIdx.y * 4;

    if (tid < 4) {
        float by[3];
        spline_b3(y0 + tid, IMG_H, by);
#pragma unroll
        for (int d = 0; d < 2; d++)
#pragma unroll
            for (int k = 0; k < 3; k++) {
                float c = 0.0f;
#pragma unroll
                for (int j = 0; j < 3; j++)
                    c = fmaf(by[j], __ldg(disp + d * 9 + j * 3 + k), c);
                sC[tid * 6 + d * 3 + k] = 5.0f * c;
            }
    }
    __syncthreads();

    int x = blockIdx.x * blockDim.x + tid;

    float bx[3];
    spline_b3(x, IMG_W, bx);

    float yy[4], xx[4];
    int iy[4], ix[4];
    float fy[4], fx[4];
#pragma unroll
    for (int p = 0; p < 4; p++) {
        float dyp = fmaf(sC[p * 6 + 0], bx[0], fmaf(sC[p * 6 + 1], bx[1], sC[p * 6 + 2] * bx[2]));
        float dxp = fmaf(sC[p * 6 + 3], bx[0], fmaf(sC[p * 6 + 4], bx[1], sC[p * 6 + 5] * bx[2]));
        yy[p] = (float)(y0 + p) + dyp;
        xx[p] = (float)x + dxp;
        float fiy = floorf(yy[p]);
        float fix = floorf(xx[p]);
        iy[p] = (int)fiy;
        ix[p] = (int)fix;
        fy[p] = yy[p] - fiy;
        fx[p] = xx[p] - fix;
    }

    float3 acc[4];

    bool share = (iy[1] == iy[0] + 1) && (iy[2] == iy[0] + 2) && (iy[3] == iy[0] + 3) &&
                 (ix[1] == ix[0]) && (ix[2] == ix[0]) && (ix[3] == ix[0]) &&
                 (iy[0] >= 1) && (iy[0] <= IMG_H - 7) &&
                 (ix[0] >= 1) && (ix[0] <= IMG_W - 3);

    if (share) {
        float wy[4][4], wx[4][4];
#pragma unroll
        for (int p = 0; p < 4; p++) {
            cubic_weights(fy[p], wy[p]);
            cubic_weights(fx[p], wx[p]);
            acc[p] = make_float3(0.f, 0.f, 0.f);
        }

        const uint2* base = g_packed + (size_t)(iy[0] - 1) * IMG_W + (ix[0] - 1);

        // Software pipeline: raw[buf] holds row r while raw[buf^1] is filling.
        uint2 raw[2][4];
#pragma unroll
        for (int b = 0; b < 4; b++) raw[0][b] = __ldg(base + b);
        base += IMG_W;

#pragma unroll
        for (int r = 0; r < 7; r++) {
            int cur = r & 1;
            if (r < 6) {
#pragma unroll
                for (int b = 0; b < 4; b++) raw[cur ^ 1][b] = __ldg(base + b);
                base += IMG_W;
            }
            float3 v[4];
            convert_row(raw[cur], v);
#pragma unroll
            for (int p = 0; p < 4; p++) {
                if (p >= r - 3 && p <= r) {
                    float3 s = rowsum(v, wx[p]);
                    float w = wy[p][r - p];
                    acc[p].x = fmaf(w, s.x, acc[p].x);
                    acc[p].y = fmaf(w, s.y, acc[p].y);
                    acc[p].z = fmaf(w, s.z, acc[p].z);
                }
            }
        }
    } else {
#pragma unroll
        for (int p = 0; p < 4; p++)
            acc[p] = sample_clamped(yy[p], xx[p]);
    }

    size_t o = ((size_t)y0 * IMG_W + x) * 3;
#pragma unroll
    for (int p = 0; p < 4; p++) {
        out[o + 0] = acc[p].x;
        out[o + 1] = acc[p].y;
        out[o + 2] = acc[p].z;
        o += (size_t)IMG_W * 3;
    }
}

extern "C" void kernel_launch(void* const* d_in, const int* in_sizes, int n_in,
                              void* d_out, int out_size) {
    const float* img  = (const float*)d_in[0];   // (2048, 4096, 3) f32
    const float* disp = (const float*)d_in[1];   // (2, 3, 3) f32
    float* out = (float*)d_out;                  // (2048, 4096, 3) f32

    int groups = IMG_H * IMG_W / 4;
    pack_kernel<<<groups / 128, 128>>>(img);

    dim3 block(128, 1, 1);
    dim3 grid(IMG_W / 128, IMG_H / 4, 1);
    warp_kernel<<<grid, block>>>(disp, out);
}

// round 10
// speedup vs baseline: 1.9809x; 1.0701x over previous
#include <cuda_runtime.h>
#include <cuda_fp16.h>

#define IMG_H 2048
#define IMG_W 4096

// 64 MB scratch: RGB0-packed fp16 image; one cubic tap = one LDG.64.
__device__ uint2 g_packed[IMG_H * IMG_W];

__device__ __forceinline__ unsigned int h2u(__half2 h) {
    return *reinterpret_cast<unsigned int*>(&h);
}
__device__ __forceinline__ __half2 u2h(unsigned int u) {
    return *reinterpret_cast<__half2*>(&u);
}

// ---------------------------------------------------------------------------
// Pass 1: pack (H,W,3) f32 -> (H,W) half4 (w unused).
// ---------------------------------------------------------------------------
__global__ void pack_kernel(const float* __restrict__ in) {
    int idx = blockIdx.x * blockDim.x + threadIdx.x;   // one per 4 pixels
    const float4* src = reinterpret_cast<const float4*>(in) + (size_t)idx * 3;
    float4 a = __ldg(src + 0);
    float4 b = __ldg(src + 1);
    float4 c = __ldg(src + 2);

    uint4 s0, s1;
    s0.x = h2u(__floats2half2_rn(a.x, a.y));
    s0.y = h2u(__floats2half2_rn(a.z, 0.0f));
    s0.z = h2u(__floats2half2_rn(a.w, b.x));
    s0.w = h2u(__floats2half2_rn(b.y, 0.0f));
    s1.x = h2u(__floats2half2_rn(b.z, b.w));
    s1.y = h2u(__floats2half2_rn(c.x, 0.0f));
    s1.z = h2u(__floats2half2_rn(c.y, c.z));
    s1.w = h2u(__floats2half2_rn(c.w, 0.0f));

    uint4* dst = reinterpret_cast<uint4*>(g_packed + (size_t)idx * 4);
    dst[0] = s0;
    dst[1] = s1;
}

// ---------------------------------------------------------------------------
// Keys cubic weights (A=-0.5), taps {i0-1..i0+2}, f in [0,1).
// ---------------------------------------------------------------------------
__device__ __forceinline__ void cubic_weights(float f, float w[4]) {
    float g = 1.0f - f;
    w[0] = -0.5f * (f * (g * g));
    w[1] = fmaf(fmaf(1.5f, f, -2.5f) * f, f, 1.0f);
    w[3] = -0.5f * (g * (f * f));
    w[2] = 1.0f - w[0] - w[1] - w[3];
}

__device__ __forceinline__ void spline_b3(int pos, int n_out, float b[3]) {
    float u = (float)(pos * 2) / (float)(n_out - 1);
    float fi = floorf(u);
    int i0 = (int)fi;
    float w[4];
    cubic_weights(u - fi, w);
    b[0] = 0.0f; b[1] = 0.0f; b[2] = 0.0f;
#pragma unroll
    for (int k = 0; k < 4; k++) {
        int t = i0 - 1 + k;
        t = min(max(t, 0), 2);
        b[t] += w[k];
    }
}

// fp16 4-tap x-reduction over one row: srg = sum wxh[b]*rg_b, sb = sum wxh[b]*b_b.
// Converts only the two row sums to f32.
__device__ __forceinline__ void rowsum_h(const uint2 raw[4], const __half2 wxh[4],
                                         float2& frg, float& fb) {
    __half2 srg = __hmul2(wxh[0], u2h(raw[0].x));
    __half2 sb  = __hmul2(wxh[0], u2h(raw[0].y));
#pragma unroll
    for (int b = 1; b < 4; b++) {
        srg = __hfma2(wxh[b], u2h(raw[b].x), srg);
        sb  = __hfma2(wxh[b], u2h(raw[b].y), sb);
    }
    frg = __half22float2(srg);
    fb  = __low2float(sb);
}

// Rare-path sampler: fully clamped 16-tap cubic, full f32. Out of hot I$ stream.
__device__ __noinline__ float3 sample_clamped(float yy, float xx) {
    float fiy = floorf(yy), fix = floorf(xx);
    int iy0 = (int)fiy, ix0 = (int)fix;
    float wy[4], wx[4];
    cubic_weights(yy - fiy, wy);
    cubic_weights(xx - fix, wx);
    int tyc[4], txc[4];
#pragma unroll
    for (int k = 0; k < 4; k++) {
        tyc[k] = min(max(iy0 - 1 + k, 0), IMG_H - 1);
        txc[k] = min(max(ix0 - 1 + k, 0), IMG_W - 1);
    }
    float3 acc = make_float3(0.f, 0.f, 0.f);
#pragma unroll
    for (int a = 0; a < 4; a++) {
        const uint2* row = g_packed + (size_t)tyc[a] * IMG_W;
        float3 s = make_float3(0.f, 0.f, 0.f);
#pragma unroll
        for (int b = 0; b < 4; b++) {
            uint2 q = __ldg(row + txc[b]);
            __half2 rg = u2h(q.x);
            __half2 bb = u2h(q.y);
            float2 frg = __half22float2(rg);
            s.x = fmaf(wx[b], frg.x, s.x);
            s.y = fmaf(wx[b], frg.y, s.y);
            s.z = fmaf(wx[b], __low2float(bb), s.z);
        }
        acc.x = fmaf(wy[a], s.x, acc.x);
        acc.y = fmaf(wy[a], s.y, acc.y);
        acc.z = fmaf(wy[a], s.z, acc.z);
    }
    return acc;
}

// ---------------------------------------------------------------------------
// Pass 2: elastic warp. One thread per VERTICAL 4-pixel quad (y0=4*by .. y0+3).
// Shared-window fast path: 7 rows serve all 4 pixels. X-reduction in fp16
// (HFMA2 on packed half2 lanes); wy weighting + cross-row accumulation in f32.
// ---------------------------------------------------------------------------
__global__ void __launch_bounds__(128, 8) warp_kernel(const float* __restrict__ disp,
                                                      float* __restrict__ out) {
    __shared__ float sC[24];   // rows y0..y0+3: c[d][k] = 5 * sum_j by[j]*D[d,j,k]

    int tid = threadIdx.x;
    int y0 = blockIdx.y * 4;

    if (tid < 4) {
        float by[3];
        spline_b3(y0 + tid, IMG_H, by);
#pragma unroll
        for (int d = 0; d < 2; d++)
#pragma unroll
            for (int k = 0; k < 3; k++) {
                float c = 0.0f;
#pragma unroll
                for (int j = 0; j < 3; j++)
                    c = fmaf(by[j], __ldg(disp + d * 9 + j * 3 + k), c);
                sC[tid * 6 + d * 3 + k] = 5.0f * c;
            }
    }
    __syncthreads();

    int x = blockIdx.x * blockDim.x + tid;

    float bx[3];
    spline_b3(x, IMG_W, bx);

    float yy[4], xx[4];
    int iy[4], ix[4];
    float fy[4], fx[4];
#pragma unroll
    for (int p = 0; p < 4; p++) {
        float dyp = fmaf(sC[p * 6 + 0], bx[0], fmaf(sC[p * 6 + 1], bx[1], sC[p * 6 + 2] * bx[2]));
        float dxp = fmaf(sC[p * 6 + 3], bx[0], fmaf(sC[p * 6 + 4], bx[1], sC[p * 6 + 5] * bx[2]));
        yy[p] = (float)(y0 + p) + dyp;
        xx[p] = (float)x + dxp;
        float fiy = floorf(yy[p]);
        float fix = floorf(xx[p]);
        iy[p] = (int)fiy;
        ix[p] = (int)fix;
        fy[p] = yy[p] - fiy;
        fx[p] = xx[p] - fix;
    }

    float3 acc[4];

    bool share = (iy[1] == iy[0] + 1) && (iy[2] == iy[0] + 2) && (iy[3] == iy[0] + 3) &&
                 (ix[1] == ix[0]) && (ix[2] == ix[0]) && (ix[3] == ix[0]) &&
                 (iy[0] >= 1) && (iy[0] <= IMG_H - 7) &&
                 (ix[0] >= 1) && (ix[0] <= IMG_W - 3);

    if (share) {
        float wy[4][4];
        __half2 wxh[4][4];
#pragma unroll
        for (int p = 0; p < 4; p++) {
            cubic_weights(fy[p], wy[p]);
            float wxf[4];
            cubic_weights(fx[p], wxf);
#pragma unroll
            for (int b = 0; b < 4; b++)
                wxh[p][b] = __float2half2_rn(wxf[b]);
            acc[p] = make_float3(0.f, 0.f, 0.f);
        }

        const uint2* base = g_packed + (size_t)(iy[0] - 1) * IMG_W + (ix[0] - 1);

        // Software pipeline: raw[buf] holds row r while raw[buf^1] is filling.
        uint2 raw[2][4];
#pragma unroll
        for (int b = 0; b < 4; b++) raw[0][b] = __ldg(base + b);
        base += IMG_W;

#pragma unroll
        for (int r = 0; r < 7; r++) {
            int cur = r & 1;
            if (r < 6) {
#pragma unroll
                for (int b = 0; b < 4; b++) raw[cur ^ 1][b] = __ldg(base + b);
                base += IMG_W;
            }
#pragma unroll
            for (int p = 0; p < 4; p++) {
                if (p >= r - 3 && p <= r) {
                    float2 frg; float fb;
                    rowsum_h(raw[cur], wxh[p], frg, fb);
                    float w = wy[p][r - p];
                    acc[p].x = fmaf(w, frg.x, acc[p].x);
                    acc[p].y = fmaf(w, frg.y, acc[p].y);
                    acc[p].z = fmaf(w, fb,    acc[p].z);
                }
            }
        }
    } else {
#pragma unroll
        for (int p = 0; p < 4; p++)
            acc[p] = sample_clamped(yy[p], xx[p]);
    }

    size_t o = ((size_t)y0 * IMG_W + x) * 3;
#pragma unroll
    for (int p = 0; p < 4; p++) {
        out[o + 0] = acc[p].x;
        out[o + 1] = acc[p].y;
        out[o + 2] = acc[p].z;
        o += (size_t)IMG_W * 3;
    }
}

extern "C" void kernel_launch(void* const* d_in, const int* in_sizes, int n_in,
                              void* d_out, int out_size) {
    const float* img  = (const float*)d_in[0];   // (2048, 4096, 3) f32
    const float* disp = (const float*)d_in[1];   // (2, 3, 3) f32
    float* out = (float*)d_out;                  // (2048, 4096, 3) f32

    int groups = IMG_H * IMG_W / 4;
    pack_kernel<<<groups / 128, 128>>>(img);

    dim3 block(128, 1, 1);
    dim3 grid(IMG_W / 128, IMG_H / 4, 1);
    warp_kernel<<<grid, block>>>(disp, out);
}